// round 3
// baseline (speedup 1.0000x reference)
#include <cuda_runtime.h>

#define NMAX   50000
#define FDIM   128
#define HDIM   64
#define NGRAPH 256

typedef unsigned long long u64;

// ------------------------- f32x2 packed helpers ----------------------------
__device__ __forceinline__ u64 pk2(float lo, float hi) {
    u64 r; asm("mov.b64 %0,{%1,%2};" : "=l"(r) : "f"(lo), "f"(hi)); return r;
}
__device__ __forceinline__ void upk2(u64 v, float& lo, float& hi) {
    asm("mov.b64 {%0,%1},%2;" : "=f"(lo), "=f"(hi) : "l"(v));
}
__device__ __forceinline__ u64 ffma2(u64 a, u64 b, u64 c) {
    u64 d; asm("fma.rn.f32x2 %0,%1,%2,%3;" : "=l"(d) : "l"(a), "l"(b), "l"(c)); return d;
}

// ------------------------- scratch (device globals) ------------------------
static __device__ float g_y   [NMAX * HDIM];
static __device__ float g_agg1[NMAX * HDIM];
static __device__ float g_h1  [NMAX * HDIM];
static __device__ float g_agg2[NMAX * HDIM];
static __device__ float g_h2  [NMAX * HDIM];
static __device__ float g_agg3[NMAX * HDIM];
static __device__ float g_h3  [NMAX * HDIM];
static __device__ float g_stats[3 * 2 * HDIM];
static __device__ float g_bn   [3 * 2 * HDIM];

// ------------------------- init: zero aggs, out = fc_b ---------------------
__global__ void k_init(float* __restrict__ out, const float* __restrict__ fc_b) {
    size_t tid    = (size_t)blockIdx.x * blockDim.x + threadIdx.x;
    size_t stride = (size_t)gridDim.x * blockDim.x;
    float4 z = make_float4(0.f, 0.f, 0.f, 0.f);
    float4* a1 = (float4*)g_agg1;
    float4* a2 = (float4*)g_agg2;
    float4* a3 = (float4*)g_agg3;
    for (size_t i = tid; i < (size_t)NMAX * HDIM / 4; i += stride) {
        a1[i] = z; a2[i] = z; a3[i] = z;
    }
    if (tid < 3 * 2 * HDIM) g_stats[tid] = 0.f;
    if (tid < NGRAPH) out[tid] = fc_b[0];
}

// =================== xform: y = x @ W1  (tiled, f32x2) =====================
// block: 64 nodes x 64 outs, 256 threads; thread: 4 nodes x 4 outs.
#define XSTR 68   // padded smem row stride (floats), 16B-aligned
static constexpr int XF_SMEM = (FDIM * HDIM * 2 + FDIM * XSTR) * 4;

__global__ void __launch_bounds__(256) k_xform(
    const float* __restrict__ x, const float* __restrict__ w1,
    float* __restrict__ y, int N)
{
    extern __shared__ float sm[];
    float* sW = sm;                       // packed {w,w}: 128*64*2 floats
    float* xs = sm + FDIM * HDIM * 2;     // x transposed: [128][XSTR]

    for (int i = threadIdx.x; i < FDIM * HDIM; i += 256) {
        float w = w1[i];
        sW[2 * i] = w; sW[2 * i + 1] = w;
    }
    int m0 = blockIdx.x * 64;
    {
        int m  = threadIdx.x >> 2;          // 0..63
        int f0 = (threadIdx.x & 3) * 32;
        int node = m0 + m;
        const float4* xr = (const float4*)(x + (size_t)node * FDIM + f0);
#pragma unroll
        for (int i = 0; i < 8; i++) {
            float4 v = (node < N) ? xr[i] : make_float4(0.f, 0.f, 0.f, 0.f);
            int f = f0 + i * 4;
            xs[(f + 0) * XSTR + m] = v.x;
            xs[(f + 1) * XSTR + m] = v.y;
            xs[(f + 2) * XSTR + m] = v.z;
            xs[(f + 3) * XSTR + m] = v.w;
        }
    }
    __syncthreads();

    int jt = (threadIdx.x & 15) * 4;
    int mt = (threadIdx.x >> 4) * 4;

    u64 acc[2][4];
#pragma unroll
    for (int p = 0; p < 2; p++)
#pragma unroll
        for (int j = 0; j < 4; j++) acc[p][j] = 0ULL;

#pragma unroll 4
    for (int k = 0; k < FDIM; k++) {
        ulonglong2 vp = *(const ulonglong2*)&xs[k * XSTR + mt];
        ulonglong2 wA = *(const ulonglong2*)&sW[(k * HDIM + jt) * 2];
        ulonglong2 wB = *(const ulonglong2*)&sW[(k * HDIM + jt) * 2 + 4];
        u64 vv[2] = { vp.x, vp.y };
        u64 ww[4] = { wA.x, wA.y, wB.x, wB.y };
#pragma unroll
        for (int p = 0; p < 2; p++)
#pragma unroll
            for (int j = 0; j < 4; j++)
                acc[p][j] = ffma2(vv[p], ww[j], acc[p][j]);
    }

#pragma unroll
    for (int p = 0; p < 2; p++) {
        float lo[4], hi[4];
#pragma unroll
        for (int j = 0; j < 4; j++) upk2(acc[p][j], lo[j], hi[j]);
        int n0 = m0 + mt + 2 * p;
        if (n0 < N)
            *(float4*)(y + (size_t)n0 * HDIM + jt) = make_float4(lo[0], lo[1], lo[2], lo[3]);
        if (n0 + 1 < N)
            *(float4*)(y + (size_t)(n0 + 1) * HDIM + jt) = make_float4(hi[0], hi[1], hi[2], hi[3]);
    }
}

// ============ MLP kernels: block 128 nodes x 64 outs, 256 threads ==========
// thread tile: 8 nodes (4 f32x2 pairs) x 4 outputs = 16 f32x2 accumulators.
#define MSTR 132  // padded smem row stride (floats), 16B-aligned
static constexpr int MLP_SMEM_FULL = (HDIM * HDIM * 2 * 2 + HDIM * MSTR) * 4;
static constexpr int MLP_SMEM_A    = (HDIM * HDIM * 2     + HDIM * MSTR) * 4;

// FULL=true : v = relu(in*sc+sh)+agg; t = relu(v@W1+b1); h = relu(t@W2+b2)
// FULL=false: v = relu(in+agg+B1);                       h = relu(v@W2+b2)
template <bool FULL>
__global__ void __launch_bounds__(256) k_mlp(
    const float* __restrict__ in, const float* __restrict__ agg,
    const float* __restrict__ sc, const float* __restrict__ sh,
    const float* __restrict__ W1, const float* __restrict__ B1,
    const float* __restrict__ W2, const float* __restrict__ B2,
    float* __restrict__ hout, int N)
{
    extern __shared__ float sm[];
    float* sWa = sm;                                     // packed first-GEMM W
    float* sWb = FULL ? sm + HDIM * HDIM * 2 : sm;       // packed second-GEMM W
    float* vs  = sm + (FULL ? HDIM * HDIM * 4 : HDIM * HDIM * 2);

    {
        const float* Wfirst = FULL ? W1 : W2;
        for (int i = threadIdx.x; i < HDIM * HDIM; i += 256) {
            float w = Wfirst[i];
            sWa[2 * i] = w; sWa[2 * i + 1] = w;
        }
        if (FULL) {
            for (int i = threadIdx.x; i < HDIM * HDIM; i += 256) {
                float w = W2[i];
                sWb[2 * i] = w; sWb[2 * i + 1] = w;
            }
        }
    }

    int m0 = blockIdx.x * 128;
    {
        int m  = threadIdx.x >> 1;           // 0..127
        int f0 = (threadIdx.x & 1) * 32;
        int node = m0 + m;
        const float4* ir = (const float4*)(in  + (size_t)node * HDIM + f0);
        const float4* ar = (const float4*)(agg + (size_t)node * HDIM + f0);
#pragma unroll
        for (int i = 0; i < 8; i++) {
            int f = f0 + i * 4;
            float4 v;
            if (node < N) {
                float4 iv = ir[i], av = ar[i];
                if (FULL) {
                    float4 a = *(const float4*)&sc[f];
                    float4 b = *(const float4*)&sh[f];
                    v.x = fmaxf(fmaf(iv.x, a.x, b.x), 0.f) + av.x;
                    v.y = fmaxf(fmaf(iv.y, a.y, b.y), 0.f) + av.y;
                    v.z = fmaxf(fmaf(iv.z, a.z, b.z), 0.f) + av.z;
                    v.w = fmaxf(fmaf(iv.w, a.w, b.w), 0.f) + av.w;
                } else {
                    float4 b = *(const float4*)&B1[f];
                    v.x = fmaxf(iv.x + av.x + b.x, 0.f);
                    v.y = fmaxf(iv.y + av.y + b.y, 0.f);
                    v.z = fmaxf(iv.z + av.z + b.z, 0.f);
                    v.w = fmaxf(iv.w + av.w + b.w, 0.f);
                }
            } else {
                v = make_float4(0.f, 0.f, 0.f, 0.f);
            }
            vs[(f + 0) * MSTR + m] = v.x;
            vs[(f + 1) * MSTR + m] = v.y;
            vs[(f + 2) * MSTR + m] = v.z;
            vs[(f + 3) * MSTR + m] = v.w;
        }
    }
    __syncthreads();

    int jt = (threadIdx.x & 15) * 4;
    int mt = (threadIdx.x >> 4) * 8;

    u64 acc[4][4];
    {
        const float* Bias = FULL ? B1 : B2;
#pragma unroll
        for (int j = 0; j < 4; j++) {
            float b = Bias[jt + j];
            u64 pb = pk2(b, b);
#pragma unroll
            for (int p = 0; p < 4; p++) acc[p][j] = pb;
        }
    }

#pragma unroll 4
    for (int k = 0; k < HDIM; k++) {
        ulonglong2 va = *(const ulonglong2*)&vs[k * MSTR + mt];
        ulonglong2 vb = *(const ulonglong2*)&vs[k * MSTR + mt + 4];
        ulonglong2 wA = *(const ulonglong2*)&sWa[(k * HDIM + jt) * 2];
        ulonglong2 wB = *(const ulonglong2*)&sWa[(k * HDIM + jt) * 2 + 4];
        u64 vv[4] = { va.x, va.y, vb.x, vb.y };
        u64 ww[4] = { wA.x, wA.y, wB.x, wB.y };
#pragma unroll
        for (int p = 0; p < 4; p++)
#pragma unroll
            for (int j = 0; j < 4; j++)
                acc[p][j] = ffma2(vv[p], ww[j], acc[p][j]);
    }

    if (FULL) {
        // t = relu(acc), restage into vs (as [j][m]), then GEMM2
        __syncthreads();
#pragma unroll
        for (int j = 0; j < 4; j++)
#pragma unroll
            for (int p = 0; p < 4; p++) {
                float lo, hi; upk2(acc[p][j], lo, hi);
                lo = fmaxf(lo, 0.f); hi = fmaxf(hi, 0.f);
                *(float2*)&vs[(jt + j) * MSTR + mt + 2 * p] = make_float2(lo, hi);
            }
        __syncthreads();

#pragma unroll
        for (int j = 0; j < 4; j++) {
            float b = B2[jt + j];
            u64 pb = pk2(b, b);
#pragma unroll
            for (int p = 0; p < 4; p++) acc[p][j] = pb;
        }
#pragma unroll 4
        for (int k = 0; k < HDIM; k++) {
            ulonglong2 va = *(const ulonglong2*)&vs[k * MSTR + mt];
            ulonglong2 vb = *(const ulonglong2*)&vs[k * MSTR + mt + 4];
            ulonglong2 wA = *(const ulonglong2*)&sWb[(k * HDIM + jt) * 2];
            ulonglong2 wB = *(const ulonglong2*)&sWb[(k * HDIM + jt) * 2 + 4];
            u64 vv[4] = { va.x, va.y, vb.x, vb.y };
            u64 ww[4] = { wA.x, wA.y, wB.x, wB.y };
#pragma unroll
            for (int p = 0; p < 4; p++)
#pragma unroll
                for (int j = 0; j < 4; j++)
                    acc[p][j] = ffma2(vv[p], ww[j], acc[p][j]);
        }
    }

    // h = relu(acc) -> global, [node][j] float4 per node
#pragma unroll
    for (int p = 0; p < 4; p++) {
        float lo[4], hi[4];
#pragma unroll
        for (int j = 0; j < 4; j++) {
            upk2(acc[p][j], lo[j], hi[j]);
            lo[j] = fmaxf(lo[j], 0.f); hi[j] = fmaxf(hi[j], 0.f);
        }
        int n0 = m0 + mt + 2 * p;
        if (n0 < N)
            *(float4*)(hout + (size_t)n0 * HDIM + jt) = make_float4(lo[0], lo[1], lo[2], lo[3]);
        if (n0 + 1 < N)
            *(float4*)(hout + (size_t)(n0 + 1) * HDIM + jt) = make_float4(hi[0], hi[1], hi[2], hi[3]);
    }
}

// --------------- layer-1 scatter on y (64-dim, plain add) ------------------
__global__ void k_scatter64p(const float* __restrict__ y, const int* __restrict__ ei,
                             float* __restrict__ agg, int E) {
    int t = blockIdx.x * blockDim.x + threadIdx.x;
    int e = t >> 4;
    if (e >= E) return;
    int l = t & 15;
    int src = ei[e];
    int dst = ei[E + e];
    float4 v = *(const float4*)(y + (size_t)src * HDIM + l * 4);
    atomicAdd((float4*)(agg + (size_t)dst * HDIM + l * 4), v);
}

// ------------------- layer-2/3 scatter (fuses BN+ReLU of source) -----------
__global__ void k_scatter64(const float* __restrict__ h, const float* __restrict__ sc,
                            const float* __restrict__ sh, const int* __restrict__ ei,
                            float* __restrict__ agg, int E) {
    int t = blockIdx.x * blockDim.x + threadIdx.x;
    int e = t >> 4;
    if (e >= E) return;
    int l = t & 15;
    int src = ei[e];
    int dst = ei[E + e];
    float4 v = *(const float4*)(h + (size_t)src * HDIM + l * 4);
    float4 a = ((const float4*)sc)[l];
    float4 b = ((const float4*)sh)[l];
    float4 r;
    r.x = fmaxf(fmaf(v.x, a.x, b.x), 0.f);
    r.y = fmaxf(fmaf(v.y, a.y, b.y), 0.f);
    r.z = fmaxf(fmaf(v.z, a.z, b.z), 0.f);
    r.w = fmaxf(fmaf(v.w, a.w, b.w), 0.f);
    atomicAdd((float4*)(agg + (size_t)dst * HDIM + l * 4), r);
}

// ----------- BN stats: per-feature sum / sumsq (float4, coalesced) ---------
__global__ void __launch_bounds__(256) k_stats(
    const float* __restrict__ h, float* __restrict__ sum,
    float* __restrict__ sumsq, int N)
{
    int f4      = threadIdx.x & 15;
    int rowLane = threadIdx.x >> 4;
    float4 s = make_float4(0.f, 0.f, 0.f, 0.f);
    float4 q = make_float4(0.f, 0.f, 0.f, 0.f);
    const float4* hv = (const float4*)h;
    for (int row = blockIdx.x * 16 + rowLane; row < N; row += gridDim.x * 16) {
        float4 v = hv[(size_t)row * 16 + f4];
        s.x += v.x; s.y += v.y; s.z += v.z; s.w += v.w;
        q.x = fmaf(v.x, v.x, q.x); q.y = fmaf(v.y, v.y, q.y);
        q.z = fmaf(v.z, v.z, q.z); q.w = fmaf(v.w, v.w, q.w);
    }
    __shared__ float4 ss[256], sq[256];
    ss[threadIdx.x] = s; sq[threadIdx.x] = q;
    __syncthreads();
#pragma unroll
    for (int off = 128; off >= 16; off >>= 1) {
        if (threadIdx.x < off) {
            float4 a = ss[threadIdx.x], b = ss[threadIdx.x + off];
            ss[threadIdx.x] = make_float4(a.x + b.x, a.y + b.y, a.z + b.z, a.w + b.w);
            float4 c = sq[threadIdx.x], d = sq[threadIdx.x + off];
            sq[threadIdx.x] = make_float4(c.x + d.x, c.y + d.y, c.z + d.z, c.w + d.w);
        }
        __syncthreads();
    }
    if (threadIdx.x < 16) {
        float4 S = ss[threadIdx.x], Q = sq[threadIdx.x];
        atomicAdd(&sum[threadIdx.x * 4 + 0], S.x);
        atomicAdd(&sum[threadIdx.x * 4 + 1], S.y);
        atomicAdd(&sum[threadIdx.x * 4 + 2], S.z);
        atomicAdd(&sum[threadIdx.x * 4 + 3], S.w);
        atomicAdd(&sumsq[threadIdx.x * 4 + 0], Q.x);
        atomicAdd(&sumsq[threadIdx.x * 4 + 1], Q.y);
        atomicAdd(&sumsq[threadIdx.x * 4 + 2], Q.z);
        atomicAdd(&sumsq[threadIdx.x * 4 + 3], Q.w);
    }
}

// ------------------------- BN finalize: scale/shift ------------------------
__global__ void k_bnfinal(const float* __restrict__ sum, const float* __restrict__ sumsq,
                          const float* __restrict__ gamma, const float* __restrict__ beta,
                          float* __restrict__ sc, float* __restrict__ sh, float invN) {
    int f = threadIdx.x;
    float mu  = sum[f] * invN;
    float var = fmaxf(sumsq[f] * invN - mu * mu, 0.f);
    float rs  = rsqrtf(var + 1e-5f);
    float s   = gamma[f] * rs;
    sc[f] = s;
    sh[f] = fmaf(-mu, s, beta[f]);
}

// -------------- final: relu(BN(h3)) dot fc_w, pooled into out[batch] -------
__global__ void k_final(const float* __restrict__ h, const float* __restrict__ sc,
                        const float* __restrict__ sh, const int* __restrict__ batch,
                        const float* __restrict__ fcw, float* __restrict__ out, int N) {
    int node = blockIdx.x * blockDim.x + threadIdx.x;
    if (node >= N) return;
    float s = 0.f;
    const float4* hr = (const float4*)(h + (size_t)node * HDIM);
#pragma unroll
    for (int k4 = 0; k4 < HDIM / 4; k4++) {
        float4 hv = hr[k4];
        float4 a  = ((const float4*)sc)[k4];
        float4 b  = ((const float4*)sh)[k4];
        float4 w  = ((const float4*)fcw)[k4];
        s = fmaf(fmaxf(fmaf(hv.x, a.x, b.x), 0.f), w.x, s);
        s = fmaf(fmaxf(fmaf(hv.y, a.y, b.y), 0.f), w.y, s);
        s = fmaf(fmaxf(fmaf(hv.z, a.z, b.z), 0.f), w.z, s);
        s = fmaf(fmaxf(fmaf(hv.w, a.w, b.w), 0.f), w.w, s);
    }
    atomicAdd(&out[batch[node]], s);
}

// ---------------------------------------------------------------------------
extern "C" void kernel_launch(void* const* d_in, const int* in_sizes, int n_in,
                              void* d_out, int out_size) {
    const float* x     = (const float*)d_in[0];
    const int*   ei    = (const int*)  d_in[1];
    const int*   batch = (const int*)  d_in[2];
    const float* c1_w1 = (const float*)d_in[3];
    const float* c1_b1 = (const float*)d_in[4];
    const float* c1_w2 = (const float*)d_in[5];
    const float* c1_b2 = (const float*)d_in[6];
    const float* c1_g  = (const float*)d_in[7];
    const float* c1_be = (const float*)d_in[8];
    const float* c2_w1 = (const float*)d_in[9];
    const float* c2_b1 = (const float*)d_in[10];
    const float* c2_w2 = (const float*)d_in[11];
    const float* c2_b2 = (const float*)d_in[12];
    const float* c2_g  = (const float*)d_in[13];
    const float* c2_be = (const float*)d_in[14];
    const float* c3_w1 = (const float*)d_in[15];
    const float* c3_b1 = (const float*)d_in[16];
    const float* c3_w2 = (const float*)d_in[17];
    const float* c3_b2 = (const float*)d_in[18];
    const float* c3_g  = (const float*)d_in[19];
    const float* c3_be = (const float*)d_in[20];
    const float* fc_w  = (const float*)d_in[21];
    const float* fc_b  = (const float*)d_in[22];
    float* out = (float*)d_out;

    int N = in_sizes[0] / FDIM;
    int E = in_sizes[1] / 2;
    float invN = 1.0f / (float)N;

    static int attr_done = 0;
    if (!attr_done) {
        cudaFuncSetAttribute(k_xform, cudaFuncAttributeMaxDynamicSharedMemorySize, XF_SMEM);
        cudaFuncSetAttribute(k_mlp<true>,  cudaFuncAttributeMaxDynamicSharedMemorySize, MLP_SMEM_FULL);
        cudaFuncSetAttribute(k_mlp<false>, cudaFuncAttributeMaxDynamicSharedMemorySize, MLP_SMEM_A);
        attr_done = 1;
    }

    float *y, *agg1, *h1, *agg2, *h2, *agg3, *h3, *stats, *bn;
    cudaGetSymbolAddress((void**)&y,     g_y);
    cudaGetSymbolAddress((void**)&agg1,  g_agg1);
    cudaGetSymbolAddress((void**)&h1,    g_h1);
    cudaGetSymbolAddress((void**)&agg2,  g_agg2);
    cudaGetSymbolAddress((void**)&h2,    g_h2);
    cudaGetSymbolAddress((void**)&agg3,  g_agg3);
    cudaGetSymbolAddress((void**)&h3,    g_h3);
    cudaGetSymbolAddress((void**)&stats, g_stats);
    cudaGetSymbolAddress((void**)&bn,    g_bn);

    int nb128 = (N + 127) / 128;
    int nb64  = (N + 63) / 64;

    k_init<<<2048, 256>>>(out, fc_b);

    // -------- layer 1 (pre-transformed) --------
    k_xform<<<nb64, 256, XF_SMEM>>>(x, c1_w1, y, N);
    k_scatter64p<<<(E * 16 + 255) / 256, 256>>>(y, ei, agg1, E);
    k_mlp<false><<<nb128, 256, MLP_SMEM_A>>>(y, agg1, nullptr, nullptr,
                                             nullptr, c1_b1, c1_w2, c1_b2, h1, N);
    k_stats<<<512, 256>>>(h1, stats + 0, stats + HDIM, N);
    k_bnfinal<<<1, HDIM>>>(stats + 0, stats + HDIM, c1_g, c1_be, bn + 0, bn + HDIM, invN);

    // -------- layer 2 --------
    k_scatter64<<<(E * 16 + 255) / 256, 256>>>(h1, bn + 0, bn + HDIM, ei, agg2, E);
    k_mlp<true><<<nb128, 256, MLP_SMEM_FULL>>>(h1, agg2, bn + 0, bn + HDIM,
                                               c2_w1, c2_b1, c2_w2, c2_b2, h2, N);
    k_stats<<<512, 256>>>(h2, stats + 2 * HDIM, stats + 3 * HDIM, N);
    k_bnfinal<<<1, HDIM>>>(stats + 2 * HDIM, stats + 3 * HDIM, c2_g, c2_be,
                           bn + 2 * HDIM, bn + 3 * HDIM, invN);

    // -------- layer 3 --------
    k_scatter64<<<(E * 16 + 255) / 256, 256>>>(h2, bn + 2 * HDIM, bn + 3 * HDIM, ei, agg3, E);
    k_mlp<true><<<nb128, 256, MLP_SMEM_FULL>>>(h2, agg3, bn + 2 * HDIM, bn + 3 * HDIM,
                                               c3_w1, c3_b1, c3_w2, c3_b2, h3, N);
    k_stats<<<512, 256>>>(h3, stats + 4 * HDIM, stats + 5 * HDIM, N);
    k_bnfinal<<<1, HDIM>>>(stats + 4 * HDIM, stats + 5 * HDIM, c3_g, c3_be,
                           bn + 4 * HDIM, bn + 5 * HDIM, invN);

    // -------- pool + head --------
    k_final<<<(N + 255) / 256, 256>>>(h3, bn + 4 * HDIM, bn + 5 * HDIM, batch, fc_w, out, N);
}